// round 16
// baseline (speedup 1.0000x reference)
#include <cuda_runtime.h>
#include <cuda_fp16.h>
#include <math.h>

#define Bq   4
#define Tq   512
#define Pq   3
#define HIDq 512
#define Hq   16
#define EXPq 512
#define Sq   1024
#define Dq   96

#define TT   128     // t rows per block (8 warps x 16)
#define TS   32      // s cols per tile
#define KS16 6       // Dq/16 k-steps for QK (fp16 k16)
#define NFV  12      // n-frags (8 cols each) for PV output
#define KHst 12      // K smem row stride (uint4)
#define QSst 28      // Q smem row stride (uint4): conflict-free
#define VROW 208     // V smem row stride (bytes) -> conflict-free ldmatrix

// ---- attn dynamic smem layout (bytes): Q panel + double-buffered K/V ----
#define A_OFF_Q  0         // uint4 [128][28] : 57,344
#define A_OFF_K0 57344     // uint4 [32][12]  : 6,144 per buf
#define A_OFF_V0 69632     // fp16 plane [32][208B] : 6,656 per buf
#define A_OFF_DD 82944     // uchar [2][32]
#define A_SMEM   83072

// ---- proj dynamic smem: K-chunk 32, padded stride, 3 CTAs/SM ----
#define P_STR    12
#define P_OFF_X0 0         // uint4 [64][12]  : 12,288 per buf
#define P_OFF_W0 24576     // uint4 [128][12] : 24,576 per buf
#define P_SMEM   73728

// Pre-split storage:
// g_Qf[bth*24 + ks*4 + tg] = (h,h,l,l) fp16x2 A-frags, d0=16ks+2tg
// g_Kh[bth*12 + ks2*4 + tg] = fp16x2 single plane, d0 = 32*ks2 + 2*tg
// g_Vh[bth*48 + d/2] = fp16x2 pair
// g_Xb, g_Wb: k16 bf16 hi/lo fragment rows for proj
__device__ uint4    g_Qf[Bq * Tq * Hq * 24];
__device__ uint4    g_Kh[Bq * Tq * Hq * 12];
__device__ unsigned g_Vh[Bq * Tq * Hq * 48];
__device__ float    g_attn[Bq * Tq * Pq * HIDq];
__device__ uint4    g_Xb[Bq * Tq * Pq * 128];
__device__ uint4    g_Wb[HIDq * 128];

__device__ __forceinline__ unsigned packbf(float lo, float hi) {
    unsigned d; asm("cvt.rn.bf16x2.f32 %0,%1,%2;" : "=r"(d) : "f"(hi), "f"(lo));
    return d;
}
__device__ __forceinline__ void splitpack(float x0, float x1, unsigned& h, unsigned& l) {
    h = packbf(x0, x1);
    float h0 = __uint_as_float(h << 16);
    float h1 = __uint_as_float(h & 0xffff0000u);
    l = packbf(x0 - h0, x1 - h1);
}
__device__ __forceinline__ unsigned pack16(float x0, float x1) {
    __half2 hh = __floats2half2_rn(x0, x1);
    return *reinterpret_cast<unsigned*>(&hh);
}
__device__ __forceinline__ void splitpack16(float x0, float x1, unsigned& h, unsigned& l) {
    __half2 hh = __floats2half2_rn(x0, x1);
    h = *reinterpret_cast<unsigned*>(&hh);
    float h0 = __low2float(hh), h1 = __high2float(hh);
    __half2 ll = __floats2half2_rn(x0 - h0, x1 - h1);
    l = *reinterpret_cast<unsigned*>(&ll);
}
__device__ __forceinline__ void mma_bf16(float* c,
    unsigned a0, unsigned a1, unsigned a2, unsigned a3,
    unsigned b0, unsigned b1)
{
    asm volatile(
        "mma.sync.aligned.m16n8k16.row.col.f32.bf16.bf16.f32 "
        "{%0,%1,%2,%3},{%4,%5,%6,%7},{%8,%9},{%0,%1,%2,%3};"
        : "+f"(c[0]), "+f"(c[1]), "+f"(c[2]), "+f"(c[3])
        : "r"(a0), "r"(a1), "r"(a2), "r"(a3), "r"(b0), "r"(b1));
}
__device__ __forceinline__ void mma_f16(float* c,
    unsigned a0, unsigned a1, unsigned a2, unsigned a3,
    unsigned b0, unsigned b1)
{
    asm volatile(
        "mma.sync.aligned.m16n8k16.row.col.f32.f16.f16.f32 "
        "{%0,%1,%2,%3},{%4,%5,%6,%7},{%8,%9},{%0,%1,%2,%3};"
        : "+f"(c[0]), "+f"(c[1]), "+f"(c[2]), "+f"(c[3])
        : "r"(a0), "r"(a1), "r"(a2), "r"(a3), "r"(b0), "r"(b1));
}
__device__ __forceinline__ void ldsm4t(uint4& v, unsigned a) {
    asm volatile(
        "ldmatrix.sync.aligned.m8n8.x4.trans.shared.b16 {%0,%1,%2,%3}, [%4];"
        : "=r"(v.x), "=r"(v.y), "=r"(v.z), "=r"(v.w) : "r"(a));
}
__device__ __forceinline__ void cpa16(unsigned dst, const void* src) {
    asm volatile("cp.async.cg.shared.global [%0], [%1], 16;\n" :: "r"(dst), "l"(src));
}
__device__ __forceinline__ void cpa_commit() {
    asm volatile("cp.async.commit_group;\n" ::: "memory");
}
__device__ __forceinline__ void cpa_wait1() {
    asm volatile("cp.async.wait_group 1;\n" ::: "memory");
}
__device__ __forceinline__ void cpa_wait0() {
    asm volatile("cp.async.wait_group 0;\n" ::: "memory");
}

// ---------------------------------------------------------------------------
// One-time presplit: K -> fp16 single-plane frags; V -> fp16 pairs.
// ---------------------------------------------------------------------------
__global__ __launch_bounds__(256) void presplit_kernel(
    const float* __restrict__ k, const float* __restrict__ v)
{
    int gidx = blockIdx.x * 256 + threadIdx.x;
    const int U = 36;
    if (gidx >= Bq * Tq * Hq * U) return;
    int u = gidx % U;
    int bth = gidx / U;
    int h = bth % Hq;
    int bt = bth / Hq;

    if (u < 12) {
        int ks2 = u >> 2, tg = u & 3;
        const float* src = &k[(bt * Pq + ks2) * HIDq + h * 32 + 2 * tg];
        float2 e0 = *(const float2*)src;
        float2 e1 = *(const float2*)(src + 8);
        float2 e2 = *(const float2*)(src + 16);
        float2 e3 = *(const float2*)(src + 24);
        g_Kh[bth * 12 + u] = make_uint4(
            pack16(e0.x, e0.y), pack16(e1.x, e1.y),
            pack16(e2.x, e2.y), pack16(e3.x, e3.y));
    } else {
        int d = (u - 12) * 4;
        float4 x = *(const float4*)&v[(bt * Pq + (d >> 5)) * HIDq + h * 32 + (d & 31)];
        unsigned* dst = &g_Vh[bth * 48 + d / 2];
        dst[0] = pack16(x.x, x.y);
        dst[1] = pack16(x.z, x.w);
    }
}

// ---------------------------------------------------------------------------
// One-time Q fp16 hi/lo split into A-fragment-native uint4 rows.
// ---------------------------------------------------------------------------
__global__ __launch_bounds__(256) void presplit_q_kernel(const float* __restrict__ q)
{
    int g = blockIdx.x * 256 + threadIdx.x;
    if (g >= Bq * Tq * Hq * 24) return;
    int u = g % 24;
    int bth = g / 24;
    int h = bth % Hq;
    int bt = bth / Hq;
    int ks = u >> 2, tg = u & 3;
    int d0 = ks * 16 + 2 * tg;
    const float* src = &q[(bt * Pq + (d0 >> 5)) * HIDq + h * 32 + (d0 & 31)];
    float2 e01 = *(const float2*)src;
    float2 e89 = *(const float2*)(src + 8);
    unsigned h0, l0, h1, l1;
    splitpack16(e01.x, e01.y, h0, l0);
    splitpack16(e89.x, e89.y, h1, l1);
    g_Qf[bth * 24 + u] = make_uint4(h0, h1, l0, l1);
}

// ---------------------------------------------------------------------------
// One-time W bf16 hi/lo split into k16 fragment rows.
// ---------------------------------------------------------------------------
__global__ __launch_bounds__(256) void presplit_w_kernel(const float* __restrict__ W)
{
    int g = blockIdx.x * 256 + threadIdx.x;
    if (g >= HIDq * 128) return;
    int n = g >> 7, j = g & 127;
    int ks = j >> 2, tg = j & 3;
    int d0 = ks * 16 + 2 * tg;
    const float* src = &W[n * HIDq + d0];
    float2 e01 = *(const float2*)src;
    float2 e89 = *(const float2*)(src + 8);
    unsigned b0h, b0l, b1h, b1l;
    splitpack(e01.x, e01.y, b0h, b0l);
    splitpack(e89.x, e89.y, b1h, b1l);
    g_Wb[n * 128 + j] = make_uint4(b0h, b1h, b0l, b1l);
}

// ---------------------------------------------------------------------------
// Fused gather + flash attention: QK 2-term FP16 (Q frags from smem),
// PV 2-term FP16. 2 CTAs/SM. Gather loop: fixed column per thread,
// one outcell load, zero integer divides.
// ---------------------------------------------------------------------------
__global__ __launch_bounds__(256, 2) void attn_kernel(
    const float* __restrict__ bias,
    const unsigned char* __restrict__ kpm, const int* __restrict__ outcell,
    const float* __restrict__ law, const unsigned char* __restrict__ emask)
{
    extern __shared__ __align__(16) char smembuf[];
    unsigned char* sDead = (unsigned char*)(smembuf + A_OFF_DD);
    unsigned sbase;
    { unsigned long long p0 = __cvta_generic_to_shared(smembuf); sbase = (unsigned)p0; }

    const int b  = blockIdx.z, h = blockIdx.y;
    const int t0 = blockIdx.x * TT;
    const int tid  = threadIdx.x;
    const int warp = tid >> 5, lane = tid & 31;
    const int gid  = lane >> 2, tig = lane & 3;
    const int rowBase = warp * 16;
    const int rlo = rowBase + gid, rhi = rlo + 8;
    const int tlo = t0 + rlo,      thi = t0 + rhi;

    const int vrow = ((lane >> 3) & 1) * 8 + (lane & 7);
    const int ncb  = (lane >> 4) * 8;

    const uint4* sQ = (const uint4*)(smembuf + A_OFF_Q);
    const int qlo = rlo * QSst + tig, qhiI = rhi * QSst + tig;

    // Gather-loop thread mapping: fixed column, 3 fixed chunk slots.
    const int gc  = tid & 31;          // s-column owned by this thread
    const int gf0 = tid >> 5;          // base chunk 0..7

    float m_lo = -3.0e38f, m_hi = -3.0e38f, l_lo = 0.f, l_hi = 0.f;
    float acc[NFV][4];
#pragma unroll
    for (int nf = 0; nf < NFV; nf++)
#pragma unroll
        for (int i = 0; i < 4; i++) acc[nf][i] = 0.f;

    auto issue_tile = [&](int it, int nb) {
        int s = it * TS + gc;
        int ts = (s < Tq) ? s : outcell[b * EXPq + (s - Tq)];
        int bth = (b * Tq + ts) * Hq + h;
        const char* ksrc = (const char*)&g_Kh[bth * 12];
        const char* vsrc = (const char*)&g_Vh[bth * 48];
        unsigned kdst = sbase + A_OFF_K0 + nb * 6144 + gc * 192;
        unsigned vdst = sbase + A_OFF_V0 + nb * 6656 + gc * VROW;
        // chunk slots gf0, gf0+8, gf0+16 cover 0..23 (12 K + 12 V)
        cpa16(kdst + gf0 * 16, ksrc + gf0 * 16);                    // f 0..7: K
        if (gf0 < 4) cpa16(kdst + (gf0 + 8) * 16, ksrc + (gf0 + 8) * 16);   // f 8..11: K
        else         cpa16(vdst + (gf0 - 4) * 16, vsrc + (gf0 - 4) * 16);   // f 12..15: V
        cpa16(vdst + (gf0 + 4) * 16, vsrc + (gf0 + 4) * 16);        // f 16..23: V
        if (tid < TS)
            sDead[nb * 32 + tid] =
                (s < Tq) ? kpm[b * Tq + s] : emask[b * EXPq + (s - Tq)];
    };

    // Load Q panel (once): 128 rows x 24 chunks; thread owns row pair pattern.
    {
        int r = tid >> 1, fb = (tid & 1) * 12;        // 2 threads per row
        unsigned qdst = sbase + A_OFF_Q + r * (QSst * 16) + fb * 16;
        const uint4* qsrc = &g_Qf[((b * Tq + t0 + r) * Hq + h) * 24 + fb];
#pragma unroll
        for (int j = 0; j < 12; j++)
            cpa16(qdst + j * 16, qsrc + j);
    }
    issue_tile(0, 0);
    cpa_commit();

    for (int it = 0; it < Sq / TS; it++) {
        const int cur = it & 1;
        if (it + 1 < Sq / TS) { issue_tile(it + 1, cur ^ 1); cpa_commit(); cpa_wait1(); }
        else                  { cpa_wait0(); }
        __syncthreads();

        const uint4* sKh = (const uint4*)(smembuf + A_OFF_K0 + cur * 6144);
        const unsigned vB = sbase + A_OFF_V0 + cur * 6656;
        const int s0 = it * TS;

        // ---- scores: C[16x32] per warp, 2-term fp16 k16; Q frags from smem
        float sc[4][4];
#pragma unroll
        for (int nf = 0; nf < 4; nf++)
#pragma unroll
            for (int i = 0; i < 4; i++) sc[nf][i] = 0.f;
#pragma unroll
        for (int ks2 = 0; ks2 < 3; ks2++) {
            int ke = 2 * ks2, ko = ke + 1;
            uint4 qeL = sQ[qlo  + ke * 4];
            uint4 qeH = sQ[qhiI + ke * 4];
            uint4 qoL = sQ[qlo  + ko * 4];
            uint4 qoH = sQ[qhiI + ko * 4];
#pragma unroll
            for (int nf = 0; nf < 4; nf++) {
                uint4 bb = sKh[(nf * 8 + gid) * KHst + ks2 * 4 + tig];
                mma_f16(sc[nf], qeL.x, qeH.x, qeL.y, qeH.y, bb.x, bb.y);
                mma_f16(sc[nf], qeL.z, qeH.z, qeL.w, qeH.w, bb.x, bb.y);
                mma_f16(sc[nf], qoL.x, qoH.x, qoL.y, qoH.y, bb.z, bb.w);
                mma_f16(sc[nf], qoL.z, qoH.z, qoL.w, qoH.w, bb.z, bb.w);
            }
        }

        // ---- bias + masks + online softmax (bias/law direct from global)
        float pw[4][4];
        float lmax_lo = -3.0e38f, lmax_hi = -3.0e38f;
#pragma unroll
        for (int nf = 0; nf < 4; nf++) {
            int colL = nf * 8 + 2 * tig;
            int col  = s0 + colL;
            float2 blo = *(const float2*)&bias[((b * Hq + h) * Tq + tlo) * Sq + col];
            float2 bhi = *(const float2*)&bias[((b * Hq + h) * Tq + thi) * Sq + col];
            float2 wlo = *(const float2*)&law [(b * Tq + tlo) * Sq + col];
            float2 whi = *(const float2*)&law [(b * Tq + thi) * Sq + col];
            unsigned char d0 = sDead[cur * 32 + colL], d1 = sDead[cur * 32 + colL + 1];

            float x, lw;
            x = sc[nf][0] + blo.x; lw = wlo.x;
            if (d0 || lw <= 1e-5f) { x = -3.0e38f; lw = 0.f; }
            sc[nf][0] = x; pw[nf][0] = lw; lmax_lo = fmaxf(lmax_lo, x);
            x = sc[nf][1] + blo.y; lw = wlo.y;
            if (d1 || lw <= 1e-5f) { x = -3.0e38f; lw = 0.f; }
            sc[nf][1] = x; pw[nf][1] = lw; lmax_lo = fmaxf(lmax_lo, x);
            x = sc[nf][2] + bhi.x; lw = whi.x;
            if (d0 || lw <= 1e-5f) { x = -3.0e38f; lw = 0.f; }
            sc[nf][2] = x; pw[nf][2] = lw; lmax_hi = fmaxf(lmax_hi, x);
            x = sc[nf][3] + bhi.y; lw = whi.y;
            if (d1 || lw <= 1e-5f) { x = -3.0e38f; lw = 0.f; }
            sc[nf][3] = x; pw[nf][3] = lw; lmax_hi = fmaxf(lmax_hi, x);
        }
#pragma unroll
        for (int o = 1; o < 4; o <<= 1) {
            lmax_lo = fmaxf(lmax_lo, __shfl_xor_sync(0xffffffffu, lmax_lo, o));
            lmax_hi = fmaxf(lmax_hi, __shfl_xor_sync(0xffffffffu, lmax_hi, o));
        }

        // ---- conditional rescale (bit-identical skip of x1.0 multiplies)
        bool upd = (lmax_lo > m_lo) | (lmax_hi > m_hi);
        if (__any_sync(0xffffffffu, upd)) {
            float nm_lo = fmaxf(m_lo, lmax_lo), nm_hi = fmaxf(m_hi, lmax_hi);
            float sl_lo = __expf(m_lo - nm_lo),  sl_hi = __expf(m_hi - nm_hi);
            m_lo = nm_lo; m_hi = nm_hi;
            l_lo *= sl_lo; l_hi *= sl_hi;
#pragma unroll
            for (int nf = 0; nf < NFV; nf++) {
                acc[nf][0] *= sl_lo; acc[nf][1] *= sl_lo;
                acc[nf][2] *= sl_hi; acc[nf][3] *= sl_hi;
            }
        }

        // ---- P = exp(w-m)*law, packed fp16 hi/lo pairs in registers.
        unsigned pH[4][2], pL[4][2];
        float es_lo = 0.f, es_hi = 0.f;
#pragma unroll
        for (int nf = 0; nf < 4; nf++) {
            float e0 = __expf(sc[nf][0] - m_lo); es_lo += e0;
            float e1 = __expf(sc[nf][1] - m_lo); es_lo += e1;
            float e2 = __expf(sc[nf][2] - m_hi); es_hi += e2;
            float e3 = __expf(sc[nf][3] - m_hi); es_hi += e3;
            float p0 = e0 * pw[nf][0], p1 = e1 * pw[nf][1];
            float p2 = e2 * pw[nf][2], p3 = e3 * pw[nf][3];
            splitpack16(p0, p1, pH[nf][0], pL[nf][0]);
            splitpack16(p2, p3, pH[nf][1], pL[nf][1]);
        }
        l_lo += es_lo;
        l_hi += es_hi;

        // ---- PV: acc[16x96] += (Ph+Pl)[16x32] * Vh[32x96], fp16 via ldmatrix
#pragma unroll
        for (int ks2 = 0; ks2 < 2; ks2++) {
            unsigned ah0 = pH[2 * ks2][0],     ah1 = pH[2 * ks2][1];
            unsigned ah2 = pH[2 * ks2 + 1][0], ah3 = pH[2 * ks2 + 1][1];
            unsigned al0 = pL[2 * ks2][0],     al1 = pL[2 * ks2][1];
            unsigned al2 = pL[2 * ks2 + 1][0], al3 = pL[2 * ks2 + 1][1];
            unsigned abase = vB + (16 * ks2 + vrow) * VROW + ncb * 2;
#pragma unroll
            for (int j = 0; j < 6; j++) {
                uint4 vh;
                ldsm4t(vh, abase + j * 32);
                mma_f16(acc[2 * j],     ah0, ah1, ah2, ah3, vh.x, vh.y);
                mma_f16(acc[2 * j],     al0, al1, al2, al3, vh.x, vh.y);
                mma_f16(acc[2 * j + 1], ah0, ah1, ah2, ah3, vh.z, vh.w);
                mma_f16(acc[2 * j + 1], al0, al1, al2, al3, vh.z, vh.w);
            }
        }
        __syncthreads();                       // all reads of buf[cur] done
    }

    // Final l reduction across the quad, then normalize.
#pragma unroll
    for (int o = 1; o < 4; o <<= 1) {
        l_lo += __shfl_xor_sync(0xffffffffu, l_lo, o);
        l_hi += __shfl_xor_sync(0xffffffffu, l_hi, o);
    }
    float rl_lo = (l_lo > 0.f) ? 1.f / l_lo : 0.f;
    float rl_hi = (l_hi > 0.f) ? 1.f / l_hi : 0.f;
#pragma unroll
    for (int nf = 0; nf < NFV; nf++) {
        int d = nf * 8 + 2 * tig;
        int p = d >> 5, j = d & 31;
        *(float2*)&g_attn[((b * Tq + tlo) * Pq + p) * HIDq + h * 32 + j] =
            make_float2(acc[nf][0] * rl_lo, acc[nf][1] * rl_lo);
        *(float2*)&g_attn[((b * Tq + thi) * Pq + p) * HIDq + h * 32 + j] =
            make_float2(acc[nf][2] * rl_hi, acc[nf][3] * rl_hi);
    }
}

// ---------------------------------------------------------------------------
// inv + scale + bf16 hi/lo split: X = attn*lnw*inv -> k16 fragment rows.
// ---------------------------------------------------------------------------
__global__ __launch_bounds__(128) void inv_split_kernel(const float* __restrict__ lnw)
{
    const int bt = blockIdx.x;
    const float* a = &g_attn[bt * Pq * HIDq];
    const int tid = threadIdx.x;
    float s = 0.f;
    for (int i = tid; i < (Pq * HIDq) / 4; i += 128) {
        float4 x = *(const float4*)&a[i * 4];
        s = fmaf(x.x, x.x, s); s = fmaf(x.y, x.y, s);
        s = fmaf(x.z, x.z, s); s = fmaf(x.w, x.w, s);
    }
#pragma unroll
    for (int o = 16; o; o >>= 1) s += __shfl_xor_sync(0xffffffffu, s, o);
    __shared__ float ws[4];
    __shared__ float sInv;
    if ((tid & 31) == 0) ws[tid >> 5] = s;
    __syncthreads();
    if (tid == 0) {
        float tot = ws[0] + ws[1] + ws[2] + ws[3];
        sInv = rsqrtf(tot * (1.0f / (float)HIDq) + 1e-3f);
    }
    __syncthreads();
    const float inv = sInv;

    for (int u = tid; u < Pq * 128; u += 128) {
        int p = u >> 7, j = u & 127;
        int ks = j >> 2, tg = j & 3;
        int d0 = ks * 16 + 2 * tg;
        const float* ap = &a[p * HIDq + d0];
        float x0 = ap[0] * lnw[d0]     * inv;
        float x1 = ap[1] * lnw[d0 + 1] * inv;
        float x8 = ap[8] * lnw[d0 + 8] * inv;
        float x9 = ap[9] * lnw[d0 + 9] * inv;
        unsigned h0, l0, h1, l1;
        splitpack(x0, x1, h0, l0);
        splitpack(x8, x9, h1, l1);
        g_Xb[(bt * Pq + p) * 128 + j] = make_uint4(h0, h1, l0, l1);
    }
}

// ---------------------------------------------------------------------------
// Projection GEMM: out[m][n] = sum_k X[m][k]*W[n][k], 3xBF16 k16.
// ---------------------------------------------------------------------------
__global__ __launch_bounds__(256, 3) void proj_kernel(float* __restrict__ out)
{
    extern __shared__ __align__(16) char smembuf[];
    unsigned sbase;
    { unsigned long long p0 = __cvta_generic_to_shared(smembuf); sbase = (unsigned)p0; }

    const int bm = blockIdx.x, bn = blockIdx.y;
    const int tid  = threadIdx.x;
    const int warp = tid >> 5, lane = tid & 31;
    const int gid  = lane >> 2, tig = lane & 3;
    const int wm = warp & 3, wn = warp >> 2;

    auto load_chunk = [&](int c, int nb) {
        unsigned xb = sbase + P_OFF_X0 + nb * 12288;
        for (int i = tid; i < 512; i += 256) {
            int r = i >> 3, f = i & 7;
            cpa16(xb + (r * P_STR + f) * 16, &g_Xb[(bm * 64 + r) * 128 + c * 8 + f]);
        }
        unsigned wb = sbase + P_OFF_W0 + nb * 24576;
        for (int i = tid; i < 1024; i += 256) {
            int r = i >> 3, f = i & 7;
            cpa16(wb + (r * P_STR + f) * 16, &g_Wb[(bn * 128 + r) * 128 + c * 8 + f]);
        }
    };

    float acc[8][4];
#pragma unroll
    for (int nf = 0; nf < 8; nf++)
#pragma unroll
        for (int i = 0; i < 4; i++) acc[nf][i] = 0.f;

    load_chunk(0, 0);
    cpa_commit();

    for (int c = 0; c < 16; c++) {
        const int cur = c & 1;
        if (c + 1 < 16) { load_chunk(c + 1, cur ^ 1); cpa_commit(); cpa_wait1(); }
        else            { cpa_wait0(); }
        __syncthreads();

        const uint4* Xs = (const uint4*)(smembuf + P_OFF_X0 + cur * 12288);
        const uint4* Wt = (const uint4*)(smembuf + P_OFF_W0 + cur * 24576);
#pragma unroll
        for (int ks = 0; ks < 2; ks++) {
            uint4 aL = Xs[(wm * 16 + gid)     * P_STR + ks * 4 + tig];
            uint4 aH = Xs[(wm * 16 + gid + 8) * P_STR + ks * 4 + tig];
#pragma unroll
            for (int nf = 0; nf < 8; nf++) {
                uint4 w4 = Wt[(wn * 64 + nf * 8 + gid) * P_STR + ks * 4 + tig];
                mma_bf16(acc[nf], aL.x, aH.x, aL.y, aH.y, w4.x, w4.y);
                mma_bf16(acc[nf], aL.z, aH.z, aL.w, aH.w, w4.x, w4.y);
                mma_bf16(acc[nf], aL.x, aH.x, aL.y, aH.y, w4.z, w4.w);
            }
        }
        __syncthreads();
    }

    const int mlo = bm * 64 + wm * 16 + gid;
    const int mhi = mlo + 8;
#pragma unroll
    for (int nf = 0; nf < 8; nf++) {
        int col = bn * 128 + wn * 64 + nf * 8 + 2 * tig;
        *(float2*)&out[mlo * HIDq + col] = make_float2(acc[nf][0], acc[nf][1]);
        *(float2*)&out[mhi * HIDq + col] = make_float2(acc[nf][2], acc[nf][3]);
    }
}

// ---------------------------------------------------------------------------
extern "C" void kernel_launch(void* const* d_in, const int* in_sizes, int n_in,
                              void* d_out, int out_size)
{
    const float* q    = (const float*)d_in[0];
    const float* k    = (const float*)d_in[1];
    const float* v    = (const float*)d_in[2];
    const float* bias = (const float*)d_in[3];
    const unsigned char* kpm   = (const unsigned char*)d_in[4];
    const int*   outcell       = (const int*)d_in[5];
    const float* law  = (const float*)d_in[6];
    const unsigned char* emask = (const unsigned char*)d_in[7];
    const float* W    = (const float*)d_in[8];
    const float* lnw  = (const float*)d_in[9];
    float* out = (float*)d_out;

    cudaFuncSetAttribute(attn_kernel,
        cudaFuncAttributeMaxDynamicSharedMemorySize, A_SMEM);
    cudaFuncSetAttribute(proj_kernel,
        cudaFuncAttributeMaxDynamicSharedMemorySize, P_SMEM);

    int units = Bq * Tq * Hq * 36;
    presplit_kernel<<<(units + 255) / 256, 256>>>(k, v);
    presplit_q_kernel<<<(Bq * Tq * Hq * 24 + 255) / 256, 256>>>(q);
    presplit_w_kernel<<<(HIDq * 128 + 255) / 256, 256>>>(W);

    dim3 g1(Tq / TT, Hq, Bq);
    attn_kernel<<<g1, 256, A_SMEM>>>(bias, kpm, outcell, law, emask);

    inv_split_kernel<<<Bq * Tq, 128>>>(lnw);

    dim3 g3((Bq * Tq * Pq) / 64, HIDq / 128);
    proj_kernel<<<g3, 256, P_SMEM>>>(out);
}

// round 17
// speedup vs baseline: 1.0481x; 1.0481x over previous
#include <cuda_runtime.h>
#include <cuda_fp16.h>
#include <math.h>

#define Bq   4
#define Tq   512
#define Pq   3
#define HIDq 512
#define Hq   16
#define EXPq 512
#define Sq   1024
#define Dq   96

#define TT   128     // t rows per block (8 warps x 16)
#define TS   32      // s cols per tile
#define KS16 6       // Dq/16 k-steps for QK (fp16 k16)
#define NFV  12      // n-frags (8 cols each) for PV output
#define KHst 12      // K smem row stride (uint4)
#define QSst 28      // Q smem row stride (uint4): conflict-free
#define VROW 208     // V smem row stride (bytes) -> conflict-free ldmatrix

// ---- attn dynamic smem layout (bytes): Q panel + double-buffered K/V ----
#define A_OFF_Q  0         // uint4 [128][28] : 57,344
#define A_OFF_K0 57344     // uint4 [32][12]  : 6,144 per buf
#define A_OFF_V0 69632     // fp16 plane [32][208B] : 6,656 per buf
#define A_OFF_DD 82944     // uchar [2][32]
#define A_SMEM   83072

// ---- proj dynamic smem: K-chunk 32, padded stride, 3 CTAs/SM ----
#define P_STR    12
#define P_OFF_X0 0         // uint4 [64][12]  : 12,288 per buf
#define P_OFF_W0 24576     // uint4 [128][12] : 24,576 per buf
#define P_SMEM   73728

// Pre-split storage:
// g_Qf[bth*24 + ks*4 + tg] = (h,h,l,l) fp16x2 A-frags, d0=16ks+2tg
// g_Kh[bth*12 + ks2*4 + tg] = fp16x2 single plane, d0 = 32*ks2 + 2*tg
// g_Vh[bth*48 + d/2] = fp16x2 pair
// g_Xb, g_Wb: k16 bf16 hi/lo fragment rows for proj
__device__ uint4    g_Qf[Bq * Tq * Hq * 24];
__device__ uint4    g_Kh[Bq * Tq * Hq * 12];
__device__ unsigned g_Vh[Bq * Tq * Hq * 48];
__device__ float    g_attn[Bq * Tq * Pq * HIDq];
__device__ uint4    g_Xb[Bq * Tq * Pq * 128];
__device__ uint4    g_Wb[HIDq * 128];

__device__ __forceinline__ unsigned packbf(float lo, float hi) {
    unsigned d; asm("cvt.rn.bf16x2.f32 %0,%1,%2;" : "=r"(d) : "f"(hi), "f"(lo));
    return d;
}
__device__ __forceinline__ void splitpack(float x0, float x1, unsigned& h, unsigned& l) {
    h = packbf(x0, x1);
    float h0 = __uint_as_float(h << 16);
    float h1 = __uint_as_float(h & 0xffff0000u);
    l = packbf(x0 - h0, x1 - h1);
}
__device__ __forceinline__ unsigned pack16(float x0, float x1) {
    __half2 hh = __floats2half2_rn(x0, x1);
    return *reinterpret_cast<unsigned*>(&hh);
}
__device__ __forceinline__ void splitpack16(float x0, float x1, unsigned& h, unsigned& l) {
    __half2 hh = __floats2half2_rn(x0, x1);
    h = *reinterpret_cast<unsigned*>(&hh);
    float h0 = __low2float(hh), h1 = __high2float(hh);
    __half2 ll = __floats2half2_rn(x0 - h0, x1 - h1);
    l = *reinterpret_cast<unsigned*>(&ll);
}
__device__ __forceinline__ void mma_bf16(float* c,
    unsigned a0, unsigned a1, unsigned a2, unsigned a3,
    unsigned b0, unsigned b1)
{
    asm volatile(
        "mma.sync.aligned.m16n8k16.row.col.f32.bf16.bf16.f32 "
        "{%0,%1,%2,%3},{%4,%5,%6,%7},{%8,%9},{%0,%1,%2,%3};"
        : "+f"(c[0]), "+f"(c[1]), "+f"(c[2]), "+f"(c[3])
        : "r"(a0), "r"(a1), "r"(a2), "r"(a3), "r"(b0), "r"(b1));
}
__device__ __forceinline__ void mma_f16(float* c,
    unsigned a0, unsigned a1, unsigned a2, unsigned a3,
    unsigned b0, unsigned b1)
{
    asm volatile(
        "mma.sync.aligned.m16n8k16.row.col.f32.f16.f16.f32 "
        "{%0,%1,%2,%3},{%4,%5,%6,%7},{%8,%9},{%0,%1,%2,%3};"
        : "+f"(c[0]), "+f"(c[1]), "+f"(c[2]), "+f"(c[3])
        : "r"(a0), "r"(a1), "r"(a2), "r"(a3), "r"(b0), "r"(b1));
}
__device__ __forceinline__ void ldsm4t(uint4& v, unsigned a) {
    asm volatile(
        "ldmatrix.sync.aligned.m8n8.x4.trans.shared.b16 {%0,%1,%2,%3}, [%4];"
        : "=r"(v.x), "=r"(v.y), "=r"(v.z), "=r"(v.w) : "r"(a));
}
__device__ __forceinline__ void cpa16(unsigned dst, const void* src) {
    asm volatile("cp.async.cg.shared.global [%0], [%1], 16;\n" :: "r"(dst), "l"(src));
}
__device__ __forceinline__ void cpa_commit() {
    asm volatile("cp.async.commit_group;\n" ::: "memory");
}
__device__ __forceinline__ void cpa_wait1() {
    asm volatile("cp.async.wait_group 1;\n" ::: "memory");
}
__device__ __forceinline__ void cpa_wait0() {
    asm volatile("cp.async.wait_group 0;\n" ::: "memory");
}

// ---------------------------------------------------------------------------
// MERGED one-time presplit: K/V + Q + W in a single launch.
//   gidx < NKV                : K (u<12) / V (u>=12) split
//   NKV <= gidx < NKV+NQ      : Q A-frag split
//   else                      : W bf16 hi/lo split
// ---------------------------------------------------------------------------
#define NKV (Bq * Tq * Hq * 36)
#define NQ  (Bq * Tq * Hq * 24)
#define NW  (HIDq * 128)

__global__ __launch_bounds__(256) void presplit_all_kernel(
    const float* __restrict__ k, const float* __restrict__ v,
    const float* __restrict__ q, const float* __restrict__ W)
{
    int gidx = blockIdx.x * 256 + threadIdx.x;
    if (gidx < NKV) {
        int u = gidx % 36;
        int bth = gidx / 36;
        int h = bth % Hq;
        int bt = bth / Hq;
        if (u < 12) {
            int ks2 = u >> 2, tg = u & 3;
            const float* src = &k[(bt * Pq + ks2) * HIDq + h * 32 + 2 * tg];
            float2 e0 = *(const float2*)src;
            float2 e1 = *(const float2*)(src + 8);
            float2 e2 = *(const float2*)(src + 16);
            float2 e3 = *(const float2*)(src + 24);
            g_Kh[bth * 12 + u] = make_uint4(
                pack16(e0.x, e0.y), pack16(e1.x, e1.y),
                pack16(e2.x, e2.y), pack16(e3.x, e3.y));
        } else {
            int d = (u - 12) * 4;
            float4 x = *(const float4*)&v[(bt * Pq + (d >> 5)) * HIDq + h * 32 + (d & 31)];
            unsigned* dst = &g_Vh[bth * 48 + d / 2];
            dst[0] = pack16(x.x, x.y);
            dst[1] = pack16(x.z, x.w);
        }
    } else if (gidx < NKV + NQ) {
        int g = gidx - NKV;
        int u = g % 24;
        int bth = g / 24;
        int h = bth % Hq;
        int bt = bth / Hq;
        int ks = u >> 2, tg = u & 3;
        int d0 = ks * 16 + 2 * tg;
        const float* src = &q[(bt * Pq + (d0 >> 5)) * HIDq + h * 32 + (d0 & 31)];
        float2 e01 = *(const float2*)src;
        float2 e89 = *(const float2*)(src + 8);
        unsigned h0, l0, h1, l1;
        splitpack16(e01.x, e01.y, h0, l0);
        splitpack16(e89.x, e89.y, h1, l1);
        g_Qf[bth * 24 + u] = make_uint4(h0, h1, l0, l1);
    } else if (gidx < NKV + NQ + NW) {
        int g = gidx - NKV - NQ;
        int n = g >> 7, j = g & 127;
        int ks = j >> 2, tg = j & 3;
        int d0 = ks * 16 + 2 * tg;
        const float* src = &W[n * HIDq + d0];
        float2 e01 = *(const float2*)src;
        float2 e89 = *(const float2*)(src + 8);
        unsigned b0h, b0l, b1h, b1l;
        splitpack(e01.x, e01.y, b0h, b0l);
        splitpack(e89.x, e89.y, b1h, b1l);
        g_Wb[n * 128 + j] = make_uint4(b0h, b1h, b0l, b1l);
    }
}

// ---------------------------------------------------------------------------
// Fused gather + flash attention: QK 2-term FP16 (Q frags from smem),
// PV 2-term FP16. 2 CTAs/SM, bias/law direct LDG. (Round-15 layout.)
// ---------------------------------------------------------------------------
__global__ __launch_bounds__(256, 2) void attn_kernel(
    const float* __restrict__ bias,
    const unsigned char* __restrict__ kpm, const int* __restrict__ outcell,
    const float* __restrict__ law, const unsigned char* __restrict__ emask)
{
    extern __shared__ __align__(16) char smembuf[];
    unsigned char* sDead = (unsigned char*)(smembuf + A_OFF_DD);
    unsigned sbase;
    { unsigned long long p0 = __cvta_generic_to_shared(smembuf); sbase = (unsigned)p0; }

    const int b  = blockIdx.z, h = blockIdx.y;
    const int t0 = blockIdx.x * TT;
    const int tid  = threadIdx.x;
    const int warp = tid >> 5, lane = tid & 31;
    const int gid  = lane >> 2, tig = lane & 3;
    const int rowBase = warp * 16;
    const int rlo = rowBase + gid, rhi = rlo + 8;
    const int tlo = t0 + rlo,      thi = t0 + rhi;

    const int vrow = ((lane >> 3) & 1) * 8 + (lane & 7);
    const int ncb  = (lane >> 4) * 8;

    const uint4* sQ = (const uint4*)(smembuf + A_OFF_Q);
    const int qlo = rlo * QSst + tig, qhiI = rhi * QSst + tig;

    float m_lo = -3.0e38f, m_hi = -3.0e38f, l_lo = 0.f, l_hi = 0.f;
    float acc[NFV][4];
#pragma unroll
    for (int nf = 0; nf < NFV; nf++)
#pragma unroll
        for (int i = 0; i < 4; i++) acc[nf][i] = 0.f;

    auto issue_tile = [&](int it, int nb) {
        int s0t = it * TS;
        unsigned kb = sbase + A_OFF_K0 + nb * 6144;
        unsigned vb = sbase + A_OFF_V0 + nb * 6656;
        for (int i = tid; i < 384; i += 256) {            // K: 32 x 12 chunks
            int c = i / 12, f = i - c * 12;
            int s = s0t + c;
            int ts = (s < Tq) ? s : outcell[b * EXPq + (s - Tq)];
            cpa16(kb + c * 192 + f * 16, &g_Kh[((b * Tq + ts) * Hq + h) * 12 + f]);
        }
        for (int i = tid; i < 384; i += 256) {            // V: 32 x 12 chunks
            int c = i / 12, f = i - c * 12;
            int s = s0t + c;
            int ts = (s < Tq) ? s : outcell[b * EXPq + (s - Tq)];
            const char* src = (const char*)&g_Vh[((b * Tq + ts) * Hq + h) * 48] + f * 16;
            cpa16(vb + c * VROW + f * 16, src);
        }
        if (tid < TS) {
            int s = s0t + tid;
            sDead[nb * 32 + tid] =
                (s < Tq) ? kpm[b * Tq + s] : emask[b * EXPq + (s - Tq)];
        }
    };

    // Load Q panel (once) + first tile in group 0.
    for (int i = tid; i < TT * 24; i += 256) {
        int r = i / 24, f = i - r * 24;
        cpa16(sbase + A_OFF_Q + (r * QSst + f) * 16,
              &g_Qf[((b * Tq + t0 + r) * Hq + h) * 24 + f]);
    }
    issue_tile(0, 0);
    cpa_commit();

    for (int it = 0; it < Sq / TS; it++) {
        const int cur = it & 1;
        if (it + 1 < Sq / TS) { issue_tile(it + 1, cur ^ 1); cpa_commit(); cpa_wait1(); }
        else                  { cpa_wait0(); }
        __syncthreads();

        const uint4* sKh = (const uint4*)(smembuf + A_OFF_K0 + cur * 6144);
        const unsigned vB = sbase + A_OFF_V0 + cur * 6656;
        const int s0 = it * TS;

        // ---- scores: C[16x32] per warp, 2-term fp16 k16; Q frags from smem
        float sc[4][4];
#pragma unroll
        for (int nf = 0; nf < 4; nf++)
#pragma unroll
            for (int i = 0; i < 4; i++) sc[nf][i] = 0.f;
#pragma unroll
        for (int ks2 = 0; ks2 < 3; ks2++) {
            int ke = 2 * ks2, ko = ke + 1;
            uint4 qeL = sQ[qlo  + ke * 4];
            uint4 qeH = sQ[qhiI + ke * 4];
            uint4 qoL = sQ[qlo  + ko * 4];
            uint4 qoH = sQ[qhiI + ko * 4];
#pragma unroll
            for (int nf = 0; nf < 4; nf++) {
                uint4 bb = sKh[(nf * 8 + gid) * KHst + ks2 * 4 + tig];
                mma_f16(sc[nf], qeL.x, qeH.x, qeL.y, qeH.y, bb.x, bb.y);
                mma_f16(sc[nf], qeL.z, qeH.z, qeL.w, qeH.w, bb.x, bb.y);
                mma_f16(sc[nf], qoL.x, qoH.x, qoL.y, qoH.y, bb.z, bb.w);
                mma_f16(sc[nf], qoL.z, qoH.z, qoL.w, qoH.w, bb.z, bb.w);
            }
        }

        // ---- bias + masks + online softmax (bias/law direct from global)
        float pw[4][4];
        float lmax_lo = -3.0e38f, lmax_hi = -3.0e38f;
#pragma unroll
        for (int nf = 0; nf < 4; nf++) {
            int colL = nf * 8 + 2 * tig;
            int col  = s0 + colL;
            float2 blo = *(const float2*)&bias[((b * Hq + h) * Tq + tlo) * Sq + col];
            float2 bhi = *(const float2*)&bias[((b * Hq + h) * Tq + thi) * Sq + col];
            float2 wlo = *(const float2*)&law [(b * Tq + tlo) * Sq + col];
            float2 whi = *(const float2*)&law [(b * Tq + thi) * Sq + col];
            unsigned char d0 = sDead[cur * 32 + colL], d1 = sDead[cur * 32 + colL + 1];

            float x, lw;
            x = sc[nf][0] + blo.x; lw = wlo.x;
            if (d0 || lw <= 1e-5f) { x = -3.0e38f; lw = 0.f; }
            sc[nf][0] = x; pw[nf][0] = lw; lmax_lo = fmaxf(lmax_lo, x);
            x = sc[nf][1] + blo.y; lw = wlo.y;
            if (d1 || lw <= 1e-5f) { x = -3.0e38f; lw = 0.f; }
            sc[nf][1] = x; pw[nf][1] = lw; lmax_lo = fmaxf(lmax_lo, x);
            x = sc[nf][2] + bhi.x; lw = whi.x;
            if (d0 || lw <= 1e-5f) { x = -3.0e38f; lw = 0.f; }
            sc[nf][2] = x; pw[nf][2] = lw; lmax_hi = fmaxf(lmax_hi, x);
            x = sc[nf][3] + bhi.y; lw = whi.y;
            if (d1 || lw <= 1e-5f) { x = -3.0e38f; lw = 0.f; }
            sc[nf][3] = x; pw[nf][3] = lw; lmax_hi = fmaxf(lmax_hi, x);
        }
#pragma unroll
        for (int o = 1; o < 4; o <<= 1) {
            lmax_lo = fmaxf(lmax_lo, __shfl_xor_sync(0xffffffffu, lmax_lo, o));
            lmax_hi = fmaxf(lmax_hi, __shfl_xor_sync(0xffffffffu, lmax_hi, o));
        }

        // ---- conditional rescale (bit-identical skip of x1.0 multiplies)
        bool upd = (lmax_lo > m_lo) | (lmax_hi > m_hi);
        if (__any_sync(0xffffffffu, upd)) {
            float nm_lo = fmaxf(m_lo, lmax_lo), nm_hi = fmaxf(m_hi, lmax_hi);
            float sl_lo = __expf(m_lo - nm_lo),  sl_hi = __expf(m_hi - nm_hi);
            m_lo = nm_lo; m_hi = nm_hi;
            l_lo *= sl_lo; l_hi *= sl_hi;
#pragma unroll
            for (int nf = 0; nf < NFV; nf++) {
                acc[nf][0] *= sl_lo; acc[nf][1] *= sl_lo;
                acc[nf][2] *= sl_hi; acc[nf][3] *= sl_hi;
            }
        }

        // ---- P = exp(w-m)*law, packed fp16 hi/lo pairs in registers.
        unsigned pH[4][2], pL[4][2];
        float es_lo = 0.f, es_hi = 0.f;
#pragma unroll
        for (int nf = 0; nf < 4; nf++) {
            float e0 = __expf(sc[nf][0] - m_lo); es_lo += e0;
            float e1 = __expf(sc[nf][1] - m_lo); es_lo += e1;
            float e2 = __expf(sc[nf][2] - m_hi); es_hi += e2;
            float e3 = __expf(sc[nf][3] - m_hi); es_hi += e3;
            float p0 = e0 * pw[nf][0], p1 = e1 * pw[nf][1];
            float p2 = e2 * pw[nf][2], p3 = e3 * pw[nf][3];
            splitpack16(p0, p1, pH[nf][0], pL[nf][0]);
            splitpack16(p2, p3, pH[nf][1], pL[nf][1]);
        }
        l_lo += es_lo;
        l_hi += es_hi;

        // ---- PV: acc[16x96] += (Ph+Pl)[16x32] * Vh[32x96], fp16 via ldmatrix
#pragma unroll
        for (int ks2 = 0; ks2 < 2; ks2++) {
            unsigned ah0 = pH[2 * ks2][0],     ah1 = pH[2 * ks2][1];
            unsigned ah2 = pH[2 * ks2 + 1][0], ah3 = pH[2 * ks2 + 1][1];
            unsigned al0 = pL[2 * ks2][0],     al1 = pL[2 * ks2][1];
            unsigned al2 = pL[2 * ks2 + 1][0], al3 = pL[2 * ks2 + 1][1];
            unsigned abase = vB + (16 * ks2 + vrow) * VROW + ncb * 2;
#pragma unroll
            for (int j = 0; j < 6; j++) {
                uint4 vh;
                ldsm4t(vh, abase + j * 32);
                mma_f16(acc[2 * j],     ah0, ah1, ah2, ah3, vh.x, vh.y);
                mma_f16(acc[2 * j],     al0, al1, al2, al3, vh.x, vh.y);
                mma_f16(acc[2 * j + 1], ah0, ah1, ah2, ah3, vh.z, vh.w);
                mma_f16(acc[2 * j + 1], al0, al1, al2, al3, vh.z, vh.w);
            }
        }
        __syncthreads();                       // all reads of buf[cur] done
    }

    // Final l reduction across the quad, then normalize.
#pragma unroll
    for (int o = 1; o < 4; o <<= 1) {
        l_lo += __shfl_xor_sync(0xffffffffu, l_lo, o);
        l_hi += __shfl_xor_sync(0xffffffffu, l_hi, o);
    }
    float rl_lo = (l_lo > 0.f) ? 1.f / l_lo : 0.f;
    float rl_hi = (l_hi > 0.f) ? 1.f / l_hi : 0.f;
#pragma unroll
    for (int nf = 0; nf < NFV; nf++) {
        int d = nf * 8 + 2 * tig;
        int p = d >> 5, j = d & 31;
        *(float2*)&g_attn[((b * Tq + tlo) * Pq + p) * HIDq + h * 32 + j] =
            make_float2(acc[nf][0] * rl_lo, acc[nf][1] * rl_lo);
        *(float2*)&g_attn[((b * Tq + thi) * Pq + p) * HIDq + h * 32 + j] =
            make_float2(acc[nf][2] * rl_hi, acc[nf][3] * rl_hi);
    }
}

// ---------------------------------------------------------------------------
// inv + scale + bf16 hi/lo split: X = attn*lnw*inv -> k16 fragment rows.
// ---------------------------------------------------------------------------
__global__ __launch_bounds__(128) void inv_split_kernel(const float* __restrict__ lnw)
{
    const int bt = blockIdx.x;
    const float* a = &g_attn[bt * Pq * HIDq];
    const int tid = threadIdx.x;
    float s = 0.f;
    for (int i = tid; i < (Pq * HIDq) / 4; i += 128) {
        float4 x = *(const float4*)&a[i * 4];
        s = fmaf(x.x, x.x, s); s = fmaf(x.y, x.y, s);
        s = fmaf(x.z, x.z, s); s = fmaf(x.w, x.w, s);
    }
#pragma unroll
    for (int o = 16; o; o >>= 1) s += __shfl_xor_sync(0xffffffffu, s, o);
    __shared__ float ws[4];
    __shared__ float sInv;
    if ((tid & 31) == 0) ws[tid >> 5] = s;
    __syncthreads();
    if (tid == 0) {
        float tot = ws[0] + ws[1] + ws[2] + ws[3];
        sInv = rsqrtf(tot * (1.0f / (float)HIDq) + 1e-3f);
    }
    __syncthreads();
    const float inv = sInv;

    for (int u = tid; u < Pq * 128; u += 128) {
        int p = u >> 7, j = u & 127;
        int ks = j >> 2, tg = j & 3;
        int d0 = ks * 16 + 2 * tg;
        const float* ap = &a[p * HIDq + d0];
        float x0 = ap[0] * lnw[d0]     * inv;
        float x1 = ap[1] * lnw[d0 + 1] * inv;
        float x8 = ap[8] * lnw[d0 + 8] * inv;
        float x9 = ap[9] * lnw[d0 + 9] * inv;
        unsigned h0, l0, h1, l1;
        splitpack(x0, x1, h0, l0);
        splitpack(x8, x9, h1, l1);
        g_Xb[(bt * Pq + p) * 128 + j] = make_uint4(h0, h1, l0, l1);
    }
}

// ---------------------------------------------------------------------------
// Projection GEMM: out[m][n] = sum_k X[m][k]*W[n][k], 3xBF16 k16.
// ---------------------------------------------------------------------------
__global__ __launch_bounds__(256, 3) void proj_kernel(float* __restrict__ out)
{
    extern __shared__ __align__(16) char smembuf[];
    unsigned sbase;
    { unsigned long long p0 = __cvta_generic_to_shared(smembuf); sbase = (unsigned)p0; }

    const int bm = blockIdx.x, bn = blockIdx.y;
    const int tid  = threadIdx.x;
    const int warp = tid >> 5, lane = tid & 31;
    const int gid  = lane >> 2, tig = lane & 3;
    const int wm = warp & 3, wn = warp >> 2;

    auto load_chunk = [&](int c, int nb) {
        unsigned xb = sbase + P_OFF_X0 + nb * 12288;
        for (int i = tid; i < 512; i += 256) {
            int r = i >> 3, f = i & 7;
            cpa16(xb + (r * P_STR + f) * 16, &g_Xb[(bm * 64 + r) * 128 + c * 8 + f]);
        }
        unsigned wb = sbase + P_OFF_W0 + nb * 24576;
        for (int i = tid; i < 1024; i += 256) {
            int r = i >> 3, f = i & 7;
            cpa16(wb + (r * P_STR + f) * 16, &g_Wb[(bn * 128 + r) * 128 + c * 8 + f]);
        }
    };

    float acc[8][4];
#pragma unroll
    for (int nf = 0; nf < 8; nf++)
#pragma unroll
        for (int i = 0; i < 4; i++) acc[nf][i] = 0.f;

    load_chunk(0, 0);
    cpa_commit();

    for (int c = 0; c < 16; c++) {
        const int cur = c & 1;
        if (c + 1 < 16) { load_chunk(c + 1, cur ^ 1); cpa_commit(); cpa_wait1(); }
        else            { cpa_wait0(); }
        __syncthreads();

        const uint4* Xs = (const uint4*)(smembuf + P_OFF_X0 + cur * 12288);
        const uint4* Wt = (const uint4*)(smembuf + P_OFF_W0 + cur * 24576);
#pragma unroll
        for (int ks = 0; ks < 2; ks++) {
            uint4 aL = Xs[(wm * 16 + gid)     * P_STR + ks * 4 + tig];
            uint4 aH = Xs[(wm * 16 + gid + 8) * P_STR + ks * 4 + tig];
#pragma unroll
            for (int nf = 0; nf < 8; nf++) {
                uint4 w4 = Wt[(wn * 64 + nf * 8 + gid) * P_STR + ks * 4 + tig];
                mma_bf16(acc[nf], aL.x, aH.x, aL.y, aH.y, w4.x, w4.y);
                mma_bf16(acc[nf], aL.z, aH.z, aL.w, aH.w, w4.x, w4.y);
                mma_bf16(acc[nf], aL.x, aH.x, aL.y, aH.y, w4.z, w4.w);
            }
        }
        __syncthreads();
    }

    const int mlo = bm * 64 + wm * 16 + gid;
    const int mhi = mlo + 8;
#pragma unroll
    for (int nf = 0; nf < 8; nf++) {
        int col = bn * 128 + wn * 64 + nf * 8 + 2 * tig;
        *(float2*)&out[mlo * HIDq + col] = make_float2(acc[nf][0], acc[nf][1]);
        *(float2*)&out[mhi * HIDq + col] = make_float2(acc[nf][2], acc[nf][3]);
    }
}

// ---------------------------------------------------------------------------
extern "C" void kernel_launch(void* const* d_in, const int* in_sizes, int n_in,
                              void* d_out, int out_size)
{
    const float* q    = (const float*)d_in[0];
    const float* k    = (const float*)d_in[1];
    const float* v    = (const float*)d_in[2];
    const float* bias = (const float*)d_in[3];
    const unsigned char* kpm   = (const unsigned char*)d_in[4];
    const int*   outcell       = (const int*)d_in[5];
    const float* law  = (const float*)d_in[6];
    const unsigned char* emask = (const unsigned char*)d_in[7];
    const float* W    = (const float*)d_in[8];
    const float* lnw  = (const float*)d_in[9];
    float* out = (float*)d_out;

    cudaFuncSetAttribute(attn_kernel,
        cudaFuncAttributeMaxDynamicSharedMemorySize, A_SMEM);
    cudaFuncSetAttribute(proj_kernel,
        cudaFuncAttributeMaxDynamicSharedMemorySize, P_SMEM);

    int total = NKV + NQ + NW;
    presplit_all_kernel<<<(total + 255) / 256, 256>>>(k, v, q, W);

    dim3 g1(Tq / TT, Hq, Bq);
    attn_kernel<<<g1, 256, A_SMEM>>>(bias, kpm, outcell, law, emask);

    inv_split_kernel<<<Bq * Tq, 128>>>(lnw);

    dim3 g3((Bq * Tq * Pq) / 64, HIDq / 128);
    proj_kernel<<<g3, 256, P_SMEM>>>(out);
}